// round 1
// baseline (speedup 1.0000x reference)
#include <cuda_runtime.h>
#include <math_constants.h>

#define NN 50000
#define EE 400000
#define BB 16

// ---------------- scratch (static device globals; no allocation) ----------------
__device__ float g_h0[NN * 64];
__device__ float g_h [NN * 64];
__device__ float g_fs[NN * 256];
__device__ float g_fd[NN * 256];
__device__ int   g_rowptr[NN + 1];
__device__ int   g_cursor[NN];
__device__ int   g_counts[NN];
__device__ int   g_col[EE];
__device__ float g_hg[BB * 64];

// ---------------- zero counters + graph accumulator ----------------
__global__ void k_zero() {
    int i = blockIdx.x * blockDim.x + threadIdx.x;
    if (i < NN) g_counts[i] = 0;
    if (i < BB * 64) g_hg[i] = 0.f;
}

// ---------------- h0 = feat @ W_in + b_in ----------------
__global__ void k_in(const float* __restrict__ feat, const float* __restrict__ Win,
                     const float* __restrict__ bin) {
    int idx = blockIdx.x * blockDim.x + threadIdx.x;
    if (idx >= NN * 64) return;
    int n = idx >> 6, d = idx & 63;
    float s = bin[d];
#pragma unroll
    for (int k = 0; k < 16; k++) s += feat[n * 16 + k] * Win[k * 64 + d];
    g_h0[idx] = s;
}

// ---------------- CSR build (keyed by dst) ----------------
__global__ void k_hist(const int* __restrict__ dst) {
    int e = blockIdx.x * blockDim.x + threadIdx.x;
    if (e < EE) atomicAdd(&g_counts[dst[e]], 1);
}

__global__ void k_scan() {  // single block, 1024 threads: exclusive scan of g_counts
    const int T = 1024;
    int t = threadIdx.x;
    const int chunk = (NN + T - 1) / T;
    int b0 = t * chunk;
    int b1 = min(b0 + chunk, NN);
    int sum = 0;
    for (int i = b0; i < b1; i++) sum += g_counts[i];

    __shared__ int ws[32];
    int lane = t & 31, wid = t >> 5;
    int v = sum;
#pragma unroll
    for (int o = 1; o < 32; o <<= 1) {
        int u = __shfl_up_sync(0xffffffffu, v, o);
        if (lane >= o) v += u;
    }
    if (lane == 31) ws[wid] = v;
    __syncthreads();
    if (wid == 0) {
        int w = ws[lane];
#pragma unroll
        for (int o = 1; o < 32; o <<= 1) {
            int u = __shfl_up_sync(0xffffffffu, w, o);
            if (lane >= o) w += u;
        }
        ws[lane] = w;
    }
    __syncthreads();
    int run = (v - sum) + (wid > 0 ? ws[wid - 1] : 0);
    for (int i = b0; i < b1; i++) {
        g_rowptr[i] = run;
        g_cursor[i] = run;
        run += g_counts[i];
    }
    if (t == 0) g_rowptr[NN] = EE;
}

__global__ void k_scatter(const int* __restrict__ src, const int* __restrict__ dst) {
    int e = blockIdx.x * blockDim.x + threadIdx.x;
    if (e < EE) {
        int pos = atomicAdd(&g_cursor[dst[e]], 1);
        g_col[pos] = src[e];
    }
}

// ---------------- fused GEMM: [h|h0] @ [W_src|W_dst] + bias -> g_fs | g_fd ------
// M=50000, K=128, Ntot=512. 128x128 CTA tile, 8x8 register microtile, KC=8.
__global__ __launch_bounds__(256, 2)
void k_gemm(int firstlayer,
            const float* __restrict__ Wsrc, const float* __restrict__ Wdst,
            const float* __restrict__ bsrc, const float* __restrict__ bdst) {
    __shared__ float As[8][128];
    __shared__ float Bs[8][128];

    const float* A0 = firstlayer ? g_h0 : g_h;  // x = concat(h, h0)
    const float* A1 = g_h0;

    int m0 = blockIdx.x * 128;
    int n0 = blockIdx.y * 128;  // 0,128 -> fs ; 256,384 -> fd
    const float* W    = (n0 < 256) ? Wsrc : Wdst;
    const float* bias = (n0 < 256) ? bsrc : bdst;
    float*       Out  = (n0 < 256) ? g_fs : g_fd;
    int cb = n0 & 255;

    int t  = threadIdx.x;
    int tx = t & 15, ty = t >> 4;

    int arow = t >> 1;
    int ako  = (t & 1) << 2;
    int grow = m0 + arow;
    int bk = t >> 5;
    int bc = (t & 31) << 2;

    float acc[8][8];
#pragma unroll
    for (int i = 0; i < 8; i++)
#pragma unroll
        for (int j = 0; j < 8; j++) acc[i][j] = 0.f;

    for (int kc = 0; kc < 128; kc += 8) {
        int k = kc + ako;  // chunk stays within one half (64 % 8 == 0)
        float4 av = make_float4(0.f, 0.f, 0.f, 0.f);
        if (grow < NN) {
            const float* Ap = (k < 64) ? (A0 + grow * 64 + k) : (A1 + grow * 64 + (k - 64));
            av = *(const float4*)Ap;
        }
        float4 bv = *(const float4*)(W + (kc + bk) * 256 + cb + bc);
        __syncthreads();
        As[ako + 0][arow] = av.x;
        As[ako + 1][arow] = av.y;
        As[ako + 2][arow] = av.z;
        As[ako + 3][arow] = av.w;
        *(float4*)&Bs[bk][bc] = bv;
        __syncthreads();
#pragma unroll
        for (int k2 = 0; k2 < 8; k2++) {
            float a[8], b[8];
#pragma unroll
            for (int i = 0; i < 8; i++) a[i] = As[k2][ty * 8 + i];
#pragma unroll
            for (int j = 0; j < 8; j++) b[j] = Bs[k2][tx * 8 + j];
#pragma unroll
            for (int i = 0; i < 8; i++)
#pragma unroll
                for (int j = 0; j < 8; j++) acc[i][j] += a[i] * b[j];
        }
    }

    float bb[8];
#pragma unroll
    for (int j = 0; j < 8; j++) bb[j] = bias[cb + tx * 8 + j];
#pragma unroll
    for (int i = 0; i < 8; i++) {
        int r = m0 + ty * 8 + i;
        if (r < NN) {
            float4 o0 = make_float4(acc[i][0] + bb[0], acc[i][1] + bb[1],
                                    acc[i][2] + bb[2], acc[i][3] + bb[3]);
            float4 o1 = make_float4(acc[i][4] + bb[4], acc[i][5] + bb[5],
                                    acc[i][6] + bb[6], acc[i][7] + bb[7]);
            *(float4*)&Out[r * 256 + cb + tx * 8]     = o0;
            *(float4*)&Out[r * 256 + cb + tx * 8 + 4] = o1;
        }
    }
}

// ---------------- edge stage: one warp per dst node, online softmax -------------
// lane owns 8 flat channels [lane*8, lane*8+8); head = lane/8.
__global__ void k_edge(const float* __restrict__ attn) {
    int gw = (blockIdx.x * blockDim.x + threadIdx.x) >> 5;
    if (gw >= NN) return;
    int lane = threadIdx.x & 31;
    int base = lane << 3;

    int beg = g_rowptr[gw];
    int end = g_rowptr[gw + 1];

    float fdv[8], av[8], acc[8];
    {
        float4 v0 = *(const float4*)&g_fd[gw * 256 + base];
        float4 v1 = *(const float4*)&g_fd[gw * 256 + base + 4];
        fdv[0] = v0.x; fdv[1] = v0.y; fdv[2] = v0.z; fdv[3] = v0.w;
        fdv[4] = v1.x; fdv[5] = v1.y; fdv[6] = v1.z; fdv[7] = v1.w;
        float4 a0 = *(const float4*)&attn[base];
        float4 a1 = *(const float4*)&attn[base + 4];
        av[0] = a0.x; av[1] = a0.y; av[2] = a0.z; av[3] = a0.w;
        av[4] = a1.x; av[5] = a1.y; av[6] = a1.z; av[7] = a1.w;
    }
#pragma unroll
    for (int i = 0; i < 8; i++) acc[i] = 0.f;
    float m = -CUDART_INF_F, sden = 0.f;

    for (int e = beg; e < end; e++) {
        int j = g_col[e];
        const float* fp = g_fs + j * 256 + base;
        float4 f0 = *(const float4*)fp;
        float4 f1 = *(const float4*)(fp + 4);
        float fsv[8] = {f0.x, f0.y, f0.z, f0.w, f1.x, f1.y, f1.z, f1.w};

        float p = 0.f;
#pragma unroll
        for (int i = 0; i < 8; i++) {
            float x = fsv[i] + fdv[i];
            x = (x > 0.f) ? x : 0.2f * x;  // LeakyReLU(0.2)
            p += av[i] * x;
        }
        p += __shfl_xor_sync(0xffffffffu, p, 1);
        p += __shfl_xor_sync(0xffffffffu, p, 2);
        p += __shfl_xor_sync(0xffffffffu, p, 4);  // per-head logit

        float mn   = fmaxf(m, p);
        float cold = __expf(m - mn);
        float w    = __expf(p - mn);
        sden = sden * cold + w;
#pragma unroll
        for (int i = 0; i < 8; i++) acc[i] = acc[i] * cold + w * fsv[i];
        m = mn;
    }

    float inv = (end > beg) ? (1.f / sden) : 0.f;
    float out[8];
#pragma unroll
    for (int i = 0; i < 8; i++) {
        float r = tanhf(acc[i] * inv);
        r += __shfl_xor_sync(0xffffffffu, r, 8);
        r += __shfl_xor_sync(0xffffffffu, r, 16);  // sum over 4 heads
        out[i] = r;
    }
    if (lane < 8) {
        float4 o0 = make_float4(out[0], out[1], out[2], out[3]);
        float4 o1 = make_float4(out[4], out[5], out[6], out[7]);
        *(float4*)&g_h[gw * 64 + base]     = o0;
        *(float4*)&g_h[gw * 64 + base + 4] = o1;
    }
}

// ---------------- graph readout: hg[b] = sum_n is_root[n]*h[n] ------------------
__global__ void k_readout(const float* __restrict__ is_root, const int* __restrict__ gid) {
    __shared__ float sh[BB * 64];
    for (int i = threadIdx.x; i < BB * 64; i += blockDim.x) sh[i] = 0.f;
    __syncthreads();
    int npb = (NN + gridDim.x - 1) / gridDim.x;
    int n0 = blockIdx.x * npb;
    int n1 = min(n0 + npb, NN);
    int d = threadIdx.x & 63;
    for (int n = n0 + (threadIdx.x >> 6); n < n1; n += (blockDim.x >> 6)) {
        float v = g_h[n * 64 + d] * is_root[n];
        atomicAdd(&sh[gid[n] * 64 + d], v);
    }
    __syncthreads();
    for (int i = threadIdx.x; i < BB * 64; i += blockDim.x) atomicAdd(&g_hg[i], sh[i]);
}

// ---------------- out = hg @ W_out + b_out ----------------
__global__ void k_out(const float* __restrict__ Wout, const float* __restrict__ bout,
                      float* __restrict__ out) {
    int t = threadIdx.x;
    if (t >= BB * 32) return;
    int b = t >> 5, o = t & 31;
    float s = bout[o];
#pragma unroll
    for (int d = 0; d < 64; d++) s += g_hg[b * 64 + d] * Wout[d * 32 + o];
    out[t] = s;
}

// ---------------- launch ----------------
extern "C" void kernel_launch(void* const* d_in, const int* in_sizes, int n_in,
                              void* d_out, int out_size) {
    const float* feat    = (const float*)d_in[0];
    const float* is_root = (const float*)d_in[1];
    const int*   src     = (const int*)d_in[2];
    const int*   dst     = (const int*)d_in[3];
    const int*   gid     = (const int*)d_in[4];
    const float* W_in    = (const float*)d_in[5];
    const float* b_in    = (const float*)d_in[6];
    const float* W_src   = (const float*)d_in[7];
    const float* b_src   = (const float*)d_in[8];
    const float* W_dst   = (const float*)d_in[9];
    const float* b_dst   = (const float*)d_in[10];
    const float* attn    = (const float*)d_in[11];
    const float* W_out   = (const float*)d_in[12];
    const float* b_out   = (const float*)d_in[13];
    float* out = (float*)d_out;

    k_zero<<<(NN + 255) / 256, 256>>>();
    k_in<<<(NN * 64 + 255) / 256, 256>>>(feat, W_in, b_in);
    k_hist<<<(EE + 255) / 256, 256>>>(dst);
    k_scan<<<1, 1024>>>();
    k_scatter<<<(EE + 255) / 256, 256>>>(src, dst);

    dim3 ggrid((NN + 127) / 128, 4);
    for (int layer = 0; layer < 4; layer++) {
        k_gemm<<<ggrid, 256>>>(layer == 0 ? 1 : 0, W_src, W_dst, b_src, b_dst);
        k_edge<<<(NN * 32 + 255) / 256, 256>>>(attn);
    }

    k_readout<<<512, 256>>>(is_root, gid);
    k_out<<<1, 512>>>(W_out, b_out, out);
}

// round 3
// speedup vs baseline: 1.3410x; 1.3410x over previous
#include <cuda_runtime.h>
#include <math_constants.h>

#define NN 50000
#define EE 400000
#define BB 16
#define SCAN_E 1024
#define SCAN_NB ((NN + SCAN_E - 1) / SCAN_E)  // 49

// ---------------- scratch (static device globals; no allocation) ----------------
__device__ float g_h0[NN * 64];
__device__ float g_h [NN * 64];
__device__ float g_fs[NN * 256];
__device__ float g_fd[NN * 256];
__device__ float g_cs[NN * 256];   // h0 @ W_src[64:] + b_src   (layer-invariant)
__device__ float g_cd[NN * 256];   // h0 @ W_dst[64:] + b_dst
__device__ int   g_rowptr[NN + 1];
__device__ int   g_cursor[NN];
__device__ int   g_counts[NN];
__device__ int   g_col[EE];
__device__ int   g_bsum[SCAN_NB];
__device__ int   g_boff[SCAN_NB];
__device__ float g_hg[BB * 64];

// ---------------- zero counters + graph accumulator ----------------
__global__ void k_zero() {
    int i = blockIdx.x * blockDim.x + threadIdx.x;
    if (i < NN) g_counts[i] = 0;
    if (i < BB * 64) g_hg[i] = 0.f;
}

// ---------------- h0 = feat @ W_in + b_in ----------------
__global__ void k_in(const float* __restrict__ feat, const float* __restrict__ Win,
                     const float* __restrict__ bin) {
    int idx = blockIdx.x * blockDim.x + threadIdx.x;
    if (idx >= NN * 64) return;
    int n = idx >> 6, d = idx & 63;
    float s = bin[d];
#pragma unroll
    for (int k = 0; k < 16; k++) s += feat[n * 16 + k] * Win[k * 64 + d];
    g_h0[idx] = s;
}

// ---------------- CSR build (keyed by dst) ----------------
__global__ void k_hist(const int* __restrict__ dst) {
    int e = blockIdx.x * blockDim.x + threadIdx.x;
    if (e < EE) atomicAdd(&g_counts[dst[e]], 1);
}

// block-local exclusive scan; writes block totals
__global__ void k_scan1() {
    __shared__ int ws[8];
    int t = threadIdx.x, b = blockIdx.x;
    int base = b * SCAN_E + t * 4;
    int v0 = 0, v1 = 0, v2 = 0, v3 = 0;
    if (base + 0 < NN) v0 = g_counts[base + 0];
    if (base + 1 < NN) v1 = g_counts[base + 1];
    if (base + 2 < NN) v2 = g_counts[base + 2];
    if (base + 3 < NN) v3 = g_counts[base + 3];
    int s = v0 + v1 + v2 + v3;
    int lane = t & 31, wid = t >> 5;
    int x = s;
#pragma unroll
    for (int o = 1; o < 32; o <<= 1) {
        int u = __shfl_up_sync(0xffffffffu, x, o);
        if (lane >= o) x += u;
    }
    if (lane == 31) ws[wid] = x;
    __syncthreads();
    if (wid == 0 && lane < 8) {
        int w = ws[lane];
#pragma unroll
        for (int o = 1; o < 8; o <<= 1) {
            int u = __shfl_up_sync(0x000000ffu, w, o);
            if (lane >= o) w += u;
        }
        ws[lane] = w;
    }
    __syncthreads();
    int excl = (x - s) + (wid > 0 ? ws[wid - 1] : 0);
    int run = excl;
    if (base + 0 < NN) { g_rowptr[base + 0] = run; run += v0; }
    if (base + 1 < NN) { g_rowptr[base + 1] = run; run += v1; }
    if (base + 2 < NN) { g_rowptr[base + 2] = run; run += v2; }
    if (base + 3 < NN) { g_rowptr[base + 3] = run; run += v3; }
    if (t == blockDim.x - 1) g_bsum[b] = excl + s;
}

// exclusive scan of 49 block sums (2 warps)
__global__ void k_scan2() {
    int t = threadIdx.x;
    __shared__ int w0tot;
    int v = (t < SCAN_NB) ? g_bsum[t] : 0;
    int lane = t & 31, wid = t >> 5;
    int x = v;
#pragma unroll
    for (int o = 1; o < 32; o <<= 1) {
        int u = __shfl_up_sync(0xffffffffu, x, o);
        if (lane >= o) x += u;
    }
    if (wid == 0 && lane == 31) w0tot = x;
    __syncthreads();
    int incl = x + (wid > 0 ? w0tot : 0);
    if (t < SCAN_NB) g_boff[t] = incl - v;
}

// add block offsets, finalize rowptr + cursor
__global__ void k_scan3() {
    int t = threadIdx.x, b = blockIdx.x;
    int off = g_boff[b];
    int base = b * SCAN_E + t * 4;
#pragma unroll
    for (int i = 0; i < 4; i++) {
        int idx = base + i;
        if (idx < NN) {
            int r = g_rowptr[idx] + off;
            g_rowptr[idx] = r;
            g_cursor[idx] = r;
        }
    }
    if (b == 0 && t == 0) g_rowptr[NN] = EE;
}

__global__ void k_scatter(const int* __restrict__ src, const int* __restrict__ dst) {
    int e = blockIdx.x * blockDim.x + threadIdx.x;
    if (e < EE) {
        int pos = atomicAdd(&g_cursor[dst[e]], 1);
        g_col[pos] = src[e];
    }
}

// ---------------- K=64 GEMM (all device-global selection via mode) --------------
// mode 0: Out(g_cs|g_cd) = g_h0 @ W[64:,:] + bias      (layer-invariant precompute)
// mode 1: Out(g_fs|g_fd) = g_h0 @ W[:64,:] + (g_cs|g_cd)   (layer 0)
// mode 2: Out(g_fs|g_fd) = g_h  @ W[:64,:] + (g_cs|g_cd)   (layers 1..3)
__global__ __launch_bounds__(256, 2)
void k_gemm64(int mode,
              const float* __restrict__ W_src, const float* __restrict__ W_dst,
              const float* __restrict__ bsrc, const float* __restrict__ bdst) {
    __shared__ float As[8][128];
    __shared__ float Bs[8][128];

    const float* A = (mode == 2) ? g_h : g_h0;

    int m0 = blockIdx.x * 128;
    int n0 = blockIdx.y * 128;
    int is_src = (n0 < 256);
    const float* Wb   = is_src ? W_src : W_dst;
    const float* W    = (mode == 0) ? (Wb + 64 * 256) : Wb;
    const float* Cm   = is_src ? g_cs : g_cd;
    const float* bias = is_src ? bsrc : bdst;
    float*       Out  = (mode == 0) ? (is_src ? g_cs : g_cd)
                                    : (is_src ? g_fs : g_fd);
    int cb = n0 & 255;

    int t  = threadIdx.x;
    int tx = t & 15, ty = t >> 4;

    int arow = t >> 1;
    int ako  = (t & 1) << 2;
    int grow = m0 + arow;
    int bk = t >> 5;
    int bc = (t & 31) << 2;

    float acc[8][8];
#pragma unroll
    for (int i = 0; i < 8; i++)
#pragma unroll
        for (int j = 0; j < 8; j++) acc[i][j] = 0.f;

    for (int kc = 0; kc < 64; kc += 8) {
        float4 av = make_float4(0.f, 0.f, 0.f, 0.f);
        if (grow < NN) av = *(const float4*)(A + grow * 64 + kc + ako);
        float4 bv = *(const float4*)(W + (kc + bk) * 256 + cb + bc);
        __syncthreads();
        As[ako + 0][arow] = av.x;
        As[ako + 1][arow] = av.y;
        As[ako + 2][arow] = av.z;
        As[ako + 3][arow] = av.w;
        *(float4*)&Bs[bk][bc] = bv;
        __syncthreads();
#pragma unroll
        for (int k2 = 0; k2 < 8; k2++) {
            float a[8], b[8];
#pragma unroll
            for (int i = 0; i < 8; i++) a[i] = As[k2][ty * 8 + i];
#pragma unroll
            for (int j = 0; j < 8; j++) b[j] = Bs[k2][tx * 8 + j];
#pragma unroll
            for (int i = 0; i < 8; i++)
#pragma unroll
                for (int j = 0; j < 8; j++) acc[i][j] += a[i] * b[j];
        }
    }

    if (mode == 0) {
        float bb[8];
#pragma unroll
        for (int j = 0; j < 8; j++) bb[j] = bias[cb + tx * 8 + j];
#pragma unroll
        for (int i = 0; i < 8; i++) {
            int r = m0 + ty * 8 + i;
            if (r < NN) {
                float4 o0 = make_float4(acc[i][0] + bb[0], acc[i][1] + bb[1],
                                        acc[i][2] + bb[2], acc[i][3] + bb[3]);
                float4 o1 = make_float4(acc[i][4] + bb[4], acc[i][5] + bb[5],
                                        acc[i][6] + bb[6], acc[i][7] + bb[7]);
                *(float4*)&Out[r * 256 + cb + tx * 8]     = o0;
                *(float4*)&Out[r * 256 + cb + tx * 8 + 4] = o1;
            }
        }
    } else {
#pragma unroll
        for (int i = 0; i < 8; i++) {
            int r = m0 + ty * 8 + i;
            if (r < NN) {
                const float* Cp = Cm + r * 256 + cb + tx * 8;
                float4 c0 = *(const float4*)Cp;
                float4 c1 = *(const float4*)(Cp + 4);
                float4 o0 = make_float4(acc[i][0] + c0.x, acc[i][1] + c0.y,
                                        acc[i][2] + c0.z, acc[i][3] + c0.w);
                float4 o1 = make_float4(acc[i][4] + c1.x, acc[i][5] + c1.y,
                                        acc[i][6] + c1.z, acc[i][7] + c1.w);
                *(float4*)&Out[r * 256 + cb + tx * 8]     = o0;
                *(float4*)&Out[r * 256 + cb + tx * 8 + 4] = o1;
            }
        }
    }
}

// ---------------- edge stage: one warp per dst node, online softmax -------------
__global__ void k_edge(const float* __restrict__ attn) {
    int gw = (blockIdx.x * blockDim.x + threadIdx.x) >> 5;
    if (gw >= NN) return;
    int lane = threadIdx.x & 31;
    int base = lane << 3;

    int beg = g_rowptr[gw];
    int end = g_rowptr[gw + 1];

    float fdv[8], av[8], acc[8];
    {
        float4 v0 = *(const float4*)&g_fd[gw * 256 + base];
        float4 v1 = *(const float4*)&g_fd[gw * 256 + base + 4];
        fdv[0] = v0.x; fdv[1] = v0.y; fdv[2] = v0.z; fdv[3] = v0.w;
        fdv[4] = v1.x; fdv[5] = v1.y; fdv[6] = v1.z; fdv[7] = v1.w;
        float4 a0 = *(const float4*)&attn[base];
        float4 a1 = *(const float4*)&attn[base + 4];
        av[0] = a0.x; av[1] = a0.y; av[2] = a0.z; av[3] = a0.w;
        av[4] = a1.x; av[5] = a1.y; av[6] = a1.z; av[7] = a1.w;
    }
#pragma unroll
    for (int i = 0; i < 8; i++) acc[i] = 0.f;
    float m = -CUDART_INF_F, sden = 0.f;

    for (int e = beg; e < end; e++) {
        int j = g_col[e];
        const float* fp = g_fs + j * 256 + base;
        float4 f0 = *(const float4*)fp;
        float4 f1 = *(const float4*)(fp + 4);
        float fsv[8] = {f0.x, f0.y, f0.z, f0.w, f1.x, f1.y, f1.z, f1.w};

        float p = 0.f;
#pragma unroll
        for (int i = 0; i < 8; i++) {
            float x = fsv[i] + fdv[i];
            x = (x > 0.f) ? x : 0.2f * x;  // LeakyReLU(0.2)
            p += av[i] * x;
        }
        p += __shfl_xor_sync(0xffffffffu, p, 1);
        p += __shfl_xor_sync(0xffffffffu, p, 2);
        p += __shfl_xor_sync(0xffffffffu, p, 4);  // per-head logit

        float mn   = fmaxf(m, p);
        float cold = __expf(m - mn);
        float w    = __expf(p - mn);
        sden = sden * cold + w;
#pragma unroll
        for (int i = 0; i < 8; i++) acc[i] = acc[i] * cold + w * fsv[i];
        m = mn;
    }

    float inv = (end > beg) ? (1.f / sden) : 0.f;
    float out[8];
#pragma unroll
    for (int i = 0; i < 8; i++) {
        float r = tanhf(acc[i] * inv);
        r += __shfl_xor_sync(0xffffffffu, r, 8);
        r += __shfl_xor_sync(0xffffffffu, r, 16);  // sum over 4 heads
        out[i] = r;
    }
    if (lane < 8) {
        float4 o0 = make_float4(out[0], out[1], out[2], out[3]);
        float4 o1 = make_float4(out[4], out[5], out[6], out[7]);
        *(float4*)&g_h[gw * 64 + base]     = o0;
        *(float4*)&g_h[gw * 64 + base + 4] = o1;
    }
}

// ---------------- graph readout: hg[b] = sum_n is_root[n]*h[n] ------------------
__global__ void k_readout(const float* __restrict__ is_root, const int* __restrict__ gid) {
    __shared__ float sh[BB * 64];
    for (int i = threadIdx.x; i < BB * 64; i += blockDim.x) sh[i] = 0.f;
    __syncthreads();
    int npb = (NN + gridDim.x - 1) / gridDim.x;
    int n0 = blockIdx.x * npb;
    int n1 = min(n0 + npb, NN);
    int d = threadIdx.x & 63;
    for (int n = n0 + (threadIdx.x >> 6); n < n1; n += (blockDim.x >> 6)) {
        float v = g_h[n * 64 + d] * is_root[n];
        atomicAdd(&sh[gid[n] * 64 + d], v);
    }
    __syncthreads();
    for (int i = threadIdx.x; i < BB * 64; i += blockDim.x) atomicAdd(&g_hg[i], sh[i]);
}

// ---------------- out = hg @ W_out + b_out ----------------
__global__ void k_out(const float* __restrict__ Wout, const float* __restrict__ bout,
                      float* __restrict__ out) {
    int t = threadIdx.x;
    if (t >= BB * 32) return;
    int b = t >> 5, o = t & 31;
    float s = bout[o];
#pragma unroll
    for (int d = 0; d < 64; d++) s += g_hg[b * 64 + d] * Wout[d * 32 + o];
    out[t] = s;
}

// ---------------- launch ----------------
extern "C" void kernel_launch(void* const* d_in, const int* in_sizes, int n_in,
                              void* d_out, int out_size) {
    const float* feat    = (const float*)d_in[0];
    const float* is_root = (const float*)d_in[1];
    const int*   src     = (const int*)d_in[2];
    const int*   dst     = (const int*)d_in[3];
    const int*   gid     = (const int*)d_in[4];
    const float* W_in    = (const float*)d_in[5];
    const float* b_in    = (const float*)d_in[6];
    const float* W_src   = (const float*)d_in[7];
    const float* b_src   = (const float*)d_in[8];
    const float* W_dst   = (const float*)d_in[9];
    const float* b_dst   = (const float*)d_in[10];
    const float* attn    = (const float*)d_in[11];
    const float* W_out   = (const float*)d_in[12];
    const float* b_out   = (const float*)d_in[13];
    float* out = (float*)d_out;

    k_zero<<<(NN + 255) / 256, 256>>>();
    k_in<<<(NN * 64 + 255) / 256, 256>>>(feat, W_in, b_in);
    k_hist<<<(EE + 255) / 256, 256>>>(dst);
    k_scan1<<<SCAN_NB, 256>>>();
    k_scan2<<<1, 64>>>();
    k_scan3<<<SCAN_NB, 256>>>();
    k_scatter<<<(EE + 255) / 256, 256>>>(src, dst);

    dim3 ggrid((NN + 127) / 128, 4);

    // precompute g_cs/g_cd = h0 @ W[64:,:] + b  (layer-invariant)
    k_gemm64<<<ggrid, 256>>>(0, W_src, W_dst, b_src, b_dst);

    for (int layer = 0; layer < 4; layer++) {
        k_gemm64<<<ggrid, 256>>>(layer == 0 ? 1 : 2, W_src, W_dst, b_src, b_dst);
        k_edge<<<(NN * 32 + 255) / 256, 256>>>(attn);
    }

    k_readout<<<512, 256>>>(is_root, gid);
    k_out<<<1, 512>>>(W_out, b_out, out);
}